// round 10
// baseline (speedup 1.0000x reference)
#include <cuda_runtime.h>
#include <cuda_bf16.h>
#include <math.h>
#include <stdint.h>

// Problem constants
#define NTOK 16384
#define DIM  2048
#define NEXP 64
#define NK   (NTOK * 2)          // 32768 (token, slot) pairs

// GEMM tiling
#define BM 64                    // tokens per CTA
#define KC 32                    // fp32 per K-chunk (2 k16 MMA steps)
#define NCHUNK (DIM / KC)        // 64
#define GTHREADS 128
#define NBLK (NTOK / BM)         // 256 CTAs
#define AD 4                     // cp.async ring depth (chunks in flight)

// Output layout: concatenation of reference return values (all as fp32)
#define OFF_TOK   0
#define OFF_REV   NK
#define OFF_CW    (2 * NK)
#define OFF_SPL   (3 * NK)
#define OFF_PROBS (3 * NK + NEXP)

// smem: [0,32K) two bf16 stages; [32K, 32K+AD*8K) A fp32 ring
#define AH_OFF 0
#define AL_OFF 4096
#define WH_OFF 8192
#define WL_OFF 12288
#define STAGE_BYTES 16384
#define RING_OFF (2 * STAGE_BYTES)
#define SMEM_DYN (RING_OFF + AD * 8192 + 1024)

// Scratch (no allocations allowed -> __device__ globals)
__device__ int g_flat_idx[NK];
__device__ int g_blockHist[NBLK * NEXP];
__device__ int g_blockBase[NBLK * NEXP];
// Pre-split W, per chunk: 4KB WH tile-layout block + 4KB WL block
__device__ unsigned char g_Wpre[NCHUNK * 8192];

// ---------------------------------------------------------------------------
__device__ __forceinline__ uint32_t smem_u32(const void* p) {
    uint32_t a;
    asm("{ .reg .u64 t; cvta.to.shared.u64 t, %1; cvt.u32.u64 %0, t; }"
        : "=r"(a) : "l"(p));
    return a;
}

#define LDMX4(r0, r1, r2, r3, addr)                                           \
    asm volatile("ldmatrix.sync.aligned.m8n8.x4.shared.b16 {%0,%1,%2,%3}, [%4];" \
        : "=r"(r0), "=r"(r1), "=r"(r2), "=r"(r3) : "r"(addr))

#define MMA_BF16(c, a0, a1, a2, a3, b0, b1)                                   \
    asm volatile(                                                             \
        "mma.sync.aligned.m16n8k16.row.col.f32.bf16.bf16.f32 "                \
        "{%0,%1,%2,%3}, {%4,%5,%6,%7}, {%8,%9}, {%0,%1,%2,%3};"               \
        : "+f"((c)[0]), "+f"((c)[1]), "+f"((c)[2]), "+f"((c)[3])              \
        : "r"(a0), "r"(a1), "r"(a2), "r"(a3), "r"(b0), "r"(b1))

#define CP_ASYNC16(dst, src)                                                  \
    asm volatile("cp.async.cg.shared.global [%0], [%1], 16;"                  \
        :: "r"(dst), "l"(src) : "memory")
#define CP_COMMIT()  asm volatile("cp.async.commit_group;" ::: "memory")
#define CP_WAIT(n)   asm volatile("cp.async.wait_group %0;" :: "n"(n) : "memory")

__device__ __forceinline__ uint32_t pack_bf16(__nv_bfloat16 a, __nv_bfloat16 b) {
    __nv_bfloat162 v; v.x = a; v.y = b;
    return *reinterpret_cast<uint32_t*>(&v);
}

__device__ __forceinline__ void split2(float x, float y, uint32_t& hi, uint32_t& lo) {
    __nv_bfloat16 hx = __float2bfloat16(x), hy = __float2bfloat16(y);
    float rx = x - __bfloat162float(hx);
    float ry = y - __bfloat162float(hy);
    hi = pack_bf16(hx, hy);
    lo = pack_bf16(__float2bfloat16(rx), __float2bfloat16(ry));
}

// ---------------------------------------------------------------------------
// Kernel 0: pre-split W into bf16 hi/lo in the swizzled tile layout.
// ---------------------------------------------------------------------------
__global__ __launch_bounds__(512) void wsplit_kernel(const float* __restrict__ W)
{
    const int t   = blockIdx.x;
    const int tid = threadIdx.x;
    const int n   = tid >> 3;
    const int c4  = tid & 7;
    const int kt  = c4 >> 1;
    const int hf  = c4 & 1;

    float4 v = *reinterpret_cast<const float4*>(W + (size_t)n * DIM + t * KC + 4 * c4);
    uint2 h, l;
    split2(v.x, v.y, h.x, l.x);
    split2(v.z, v.w, h.y, l.y);
    uint32_t off = (uint32_t)((kt * 8 + (n >> 3)) * 128 +
                              (((n & 7) ^ (kt << 1)) << 4) + hf * 8);
    *reinterpret_cast<uint2*>(g_Wpre + (size_t)t * 8192 + off) = h;
    *reinterpret_cast<uint2*>(g_Wpre + (size_t)t * 8192 + 4096 + off) = l;
}

// ---------------------------------------------------------------------------
// Kernel 1: deep-cp.async A ring + bf16-split GEMM + softmax + top-2 + probs.
// ---------------------------------------------------------------------------
__global__ __launch_bounds__(GTHREADS, 2) void gate_gemm_kernel(
    const float* __restrict__ A,   // [NTOK, DIM]
    float* __restrict__ out)
{
    extern __shared__ char dynsm[];
    char* sbase = (char*)(((uintptr_t)dynsm + 1023) & ~(uintptr_t)1023);
    const uint32_t sb = smem_u32(sbase);

    __shared__ int hist[NEXP];

    const int tid  = threadIdx.x;
    const int wid  = tid >> 5;
    const int lane = tid & 31;
    const int g    = lane >> 2;
    const int q    = lane & 3;
    const int lg   = lane >> 3;
    const int lr   = lane & 7;
    const int mG   = wid >> 1;
    const int nG   = wid & 1;
    const int blk  = blockIdx.x;
    const int tok0 = blk * BM;

    if (tid < NEXP) hist[tid] = 0;

    // ---- producer geometry -------------------------------------------------
    const int prow = tid >> 3;        // 0..15
    const int c4   = tid & 7;
    const int kt_p = c4 >> 1;
    const int hf_p = c4 & 1;

    const float4* Ap[4];
    uint32_t stOff[4];
    uint32_t rgOff[4];                // ring byte offset per p
#pragma unroll
    for (int p = 0; p < 4; ++p) {
        int r = prow + 16 * p;
        Ap[p] = reinterpret_cast<const float4*>(A + (size_t)(tok0 + r) * DIM + 4 * c4);
        stOff[p] = (uint32_t)((kt_p * 8 + (r >> 3)) * 128 +
                              (((r & 7) ^ (kt_p << 1)) << 4) + hf_p * 8);
        rgOff[p] = (uint32_t)(r * 128 + c4 * 16);
    }

    // A: cp.async fp32 chunk c into ring slot c%AD
    auto cpA = [&](int c) {
        const uint32_t base = sb + RING_OFF + (uint32_t)((c & (AD - 1)) * 8192);
#pragma unroll
        for (int p = 0; p < 4; ++p)
            CP_ASYNC16(base + rgOff[p], (const void*)(Ap[p] + c * 8));
    };
    // convert fp32 ring chunk c -> bf16 stage c&1
    auto convA = [&](int c) {
        char* ring = sbase + RING_OFF + (c & (AD - 1)) * 8192;
        char* stg  = sbase + (c & 1) * STAGE_BYTES;
#pragma unroll
        for (int p = 0; p < 4; ++p) {
            float4 v = *reinterpret_cast<const float4*>(ring + rgOff[p]);
            uint2 h, l;
            split2(v.x, v.y, h.x, l.x);
            split2(v.z, v.w, h.y, l.y);
            *reinterpret_cast<uint2*>(stg + AH_OFF + stOff[p]) = h;
            *reinterpret_cast<uint2*>(stg + AL_OFF + stOff[p]) = l;
        }
    };
    // W: register prefetch from pre-split buffer (L2), raw copy to stage
    uint4 wreg[4];
    auto ldW = [&](int c) {
        const uint4* src = reinterpret_cast<const uint4*>(g_Wpre + (size_t)c * 8192 + tid * 64);
#pragma unroll
        for (int gg = 0; gg < 4; ++gg) wreg[gg] = src[gg];
    };
    auto stW = [&](int s) {
        uint4* dst = reinterpret_cast<uint4*>(sbase + s * STAGE_BYTES + WH_OFF + tid * 64);
#pragma unroll
        for (int gg = 0; gg < 4; ++gg) dst[gg] = wreg[gg];
    };

    float acc[2][4][4];
#pragma unroll
    for (int mt = 0; mt < 2; ++mt)
#pragma unroll
        for (int nt = 0; nt < 4; ++nt)
#pragma unroll
            for (int c = 0; c < 4; ++c) acc[mt][nt][c] = 0.f;

    const uint32_t aRt = (uint32_t)((4 * mG + (lg & 1)) * 128);
    const uint32_t wRt = (uint32_t)((4 * nG + (lg >> 1)) * 128);

    // ---- prologue ----------------------------------------------------------
#pragma unroll
    for (int c = 0; c < AD; ++c) { cpA(c); CP_COMMIT(); }
    ldW(0);
    CP_WAIT(AD - 1);                  // chunk 0 resident
    convA(0);
    stW(0);
    ldW(1);
    __syncthreads();

    // ---- mainloop ----------------------------------------------------------
    for (int t = 0; t < NCHUNK; ++t) {
        if (t + AD < NCHUNK) cpA(t + AD);
        CP_COMMIT();                  // possibly empty group (keeps count uniform)

        if (t + 1 < NCHUNK) {
            CP_WAIT(AD - 1);          // chunk t+1 resident
            convA(t + 1);
            stW((t + 1) & 1);
            if (t + 2 < NCHUNK) ldW(t + 2);
        }

        const uint32_t stg = sb + (uint32_t)((t & 1) * STAGE_BYTES);
#pragma unroll
        for (int ks = 0; ks < 2; ++ks) {
            const int ktA = 2 * ks + (lg >> 1);
            const int ktW = 2 * ks + (lg & 1);
            const uint32_t aAddr = stg + (uint32_t)(ktA * 1024) +
                                   (uint32_t)((lr ^ (ktA << 1)) << 4) + aRt;
            const uint32_t wAddr = stg + WH_OFF + (uint32_t)(ktW * 1024) +
                                   (uint32_t)((lr ^ (ktW << 1)) << 4) + wRt;

            uint32_t ah[8], al[8], wh[8], wl[8];
            LDMX4(ah[0], ah[1], ah[2], ah[3], aAddr);
            LDMX4(ah[4], ah[5], ah[6], ah[7], aAddr + 256);
            LDMX4(al[0], al[1], al[2], al[3], aAddr + AL_OFF);
            LDMX4(al[4], al[5], al[6], al[7], aAddr + AL_OFF + 256);
            LDMX4(wh[0], wh[1], wh[2], wh[3], wAddr);
            LDMX4(wh[4], wh[5], wh[6], wh[7], wAddr + 256);
            LDMX4(wl[0], wl[1], wl[2], wl[3], wAddr + 4096);
            LDMX4(wl[4], wl[5], wl[6], wl[7], wAddr + 4096 + 256);

#pragma unroll
            for (int nt = 0; nt < 4; ++nt) {
                const uint32_t bh0 = wh[2 * nt], bh1 = wh[2 * nt + 1];
                const uint32_t bl0 = wl[2 * nt], bl1 = wl[2 * nt + 1];
#pragma unroll
                for (int mt = 0; mt < 2; ++mt) {
                    uint32_t* aH = &ah[4 * mt];
                    uint32_t* aL = &al[4 * mt];
                    MMA_BF16(acc[mt][nt], aH[0], aH[1], aH[2], aH[3], bh0, bh1);
                    MMA_BF16(acc[mt][nt], aH[0], aH[1], aH[2], aH[3], bl0, bl1);
                    MMA_BF16(acc[mt][nt], aL[0], aL[1], aL[2], aL[3], bh0, bh1);
                }
            }
        }
        __syncthreads();
    }

    // ---- epilogue: logits -> Cs (reuse stage smem) -------------------------
    float* Cs = reinterpret_cast<float*>(sbase);      // [64][66]
#pragma unroll
    for (int mt = 0; mt < 2; ++mt)
#pragma unroll
        for (int nt = 0; nt < 4; ++nt) {
            int row = 32 * mG + 16 * mt + g;
            int col = 32 * nG + 8 * nt + 2 * q;
            *reinterpret_cast<float2*>(&Cs[row * 66 + col]) =
                make_float2(acc[mt][nt][0], acc[mt][nt][1]);
            *reinterpret_cast<float2*>(&Cs[(row + 8) * 66 + col]) =
                make_float2(acc[mt][nt][2], acc[mt][nt][3]);
        }
    __syncthreads();

    if (tid < BM) {                     // one thread per token
        const int t = tid;
        float f[64];
        float mx = -1e30f;
#pragma unroll
        for (int e = 0; e < NEXP; e++) { f[e] = Cs[t * 66 + e]; mx = fmaxf(mx, f[e]); }
        float ssum = 0.f;
#pragma unroll
        for (int e = 0; e < NEXP; e++) { f[e] = expf(f[e] - mx); ssum += f[e]; }
        float inv = 1.0f / ssum;
        float v1 = -1.f, v2 = -1.f;
        int i1 = 0, i2 = 0;
#pragma unroll
        for (int e = 0; e < NEXP; e++) {
            float p = f[e] * inv;
            Cs[t * 66 + e] = p;
            if (p > v1)      { v2 = v1; i2 = i1; v1 = p; i1 = e; }
            else if (p > v2) { v2 = p; i2 = e; }
        }
        // combine = softmax over the top-2 prob VALUES (reference quirk)
        float eb = expf(v2 - v1);
        float invd = 1.0f / (1.0f + eb);
        const int token = tok0 + t;
        const int flat = token * 2;
        out[OFF_CW + flat]     = invd;
        out[OFF_CW + flat + 1] = eb * invd;
        g_flat_idx[flat]     = i1;
        g_flat_idx[flat + 1] = i2;
        atomicAdd(&hist[i1], 1);
        atomicAdd(&hist[i2], 1);
    }
    __syncthreads();

    if (tid < NEXP) g_blockHist[blk * NEXP + tid] = hist[tid];

    // coalesced probs writeback
    float* pout = out + OFF_PROBS + (size_t)tok0 * NEXP;
    for (int idx = tid; idx < BM * NEXP; idx += GTHREADS) {
        int tt = idx >> 6, e = idx & 63;
        pout[idx] = Cs[tt * 66 + e];
    }
}

// ---------------------------------------------------------------------------
// Kernel 2 (1 CTA, 1024 threads): per-expert scan across blocks + offsets
// ---------------------------------------------------------------------------
#define CHUNKB (NBLK / 16)       // 16 blocks per chunk
__global__ __launch_bounds__(1024) void gate_scan_kernel(float* __restrict__ out)
{
    __shared__ int part[16][NEXP];
    __shared__ int totals[NEXP];
    __shared__ int offs[NEXP];
    const int tid = threadIdx.x;
    const int e = tid & 63;
    const int c = tid >> 6;          // chunk 0..15

    int s = 0;
#pragma unroll
    for (int b = c * CHUNKB; b < (c + 1) * CHUNKB; b++) s += g_blockHist[b * NEXP + e];
    part[c][e] = s;
    __syncthreads();

    if (tid < NEXP) {
        int run = 0;
#pragma unroll
        for (int cc = 0; cc < 16; cc++) run += part[cc][e];
        totals[e] = run;
        out[OFF_SPL + e] = (float)run;
    }
    __syncthreads();

    if (tid == 0) {
        int a = 0;
        for (int i = 0; i < NEXP; i++) { offs[i] = a; a += totals[i]; }
    }
    __syncthreads();

    int base = offs[e];
    for (int cc = 0; cc < c; cc++) base += part[cc][e];
#pragma unroll
    for (int b = c * CHUNKB; b < (c + 1) * CHUNKB; b++) {
        g_blockBase[b * NEXP + e] = base;
        base += g_blockHist[b * NEXP + e];
    }
}

// ---------------------------------------------------------------------------
// Kernel 3 (NBLK x 128): stable intra-block rank + scatter.
// ---------------------------------------------------------------------------
__global__ __launch_bounds__(128) void gate_scatter_kernel(float* __restrict__ out)
{
    __shared__ int warpHist[4][NEXP];
    __shared__ int base_s[NEXP];
    const int tid  = threadIdx.x;
    const int blk  = blockIdx.x;
    const int w    = tid >> 5;
    const int lane = tid & 31;

    if (tid < NEXP) base_s[tid] = g_blockBase[blk * NEXP + tid];
    for (int i = tid; i < 4 * NEXP; i += 128) (&warpHist[0][0])[i] = 0;
    __syncthreads();

    const int flat = blk * 128 + tid;
    const int e    = g_flat_idx[flat];

    unsigned m     = __match_any_sync(0xffffffffu, e);
    unsigned below = m & ((1u << lane) - 1u);
    int rank = __popc(below);
    if (below == 0) warpHist[w][e] = __popc(m);     // lowest lane of group
    __syncthreads();

    int prev = 0;
#pragma unroll
    for (int ww = 0; ww < 3; ++ww)
        if (ww < w) prev += warpHist[ww][e];

    const int pos = base_s[e] + prev + rank;
    out[OFF_TOK + pos]  = (float)(flat >> 1);       // token index
    out[OFF_REV + flat] = (float)pos;               // sorted position of flat idx
}

// ---------------------------------------------------------------------------
extern "C" void kernel_launch(void* const* d_in, const int* in_sizes, int n_in,
                              void* d_out, int out_size)
{
    const float* A = (const float*)d_in[0];   // inputs    [16384, 2048] fp32
    const float* W = (const float*)d_in[1];   // wg_weight [64, 2048]    fp32
    float* out = (float*)d_out;

    cudaFuncSetAttribute(gate_gemm_kernel,
                         cudaFuncAttributeMaxDynamicSharedMemorySize, SMEM_DYN);

    wsplit_kernel<<<NCHUNK, 512>>>(W);
    gate_gemm_kernel<<<NBLK, GTHREADS, SMEM_DYN>>>(A, out);
    gate_scan_kernel<<<1, 1024>>>(out);
    gate_scatter_kernel<<<NK / 128, 128>>>(out);
}

// round 11
// speedup vs baseline: 1.0762x; 1.0762x over previous
#include <cuda_runtime.h>
#include <cuda_bf16.h>
#include <math.h>
#include <stdint.h>

// Problem constants
#define NTOK 16384
#define DIM  2048
#define NEXP 64
#define NK   (NTOK * 2)          // 32768 (token, slot) pairs

// GEMM tiling
#define BM 32                    // tokens per CTA
#define KC 32                    // fp32 per K-chunk (2 k16 MMA steps)
#define NCHUNK (DIM / KC)        // 64
#define GTHREADS 128
#define NBLK (NTOK / BM)         // 512 CTAs

// Output layout: concatenation of reference return values (all as fp32)
#define OFF_TOK   0
#define OFF_REV   NK
#define OFF_CW    (2 * NK)
#define OFF_SPL   (3 * NK)
#define OFF_PROBS (3 * NK + NEXP)

// smem stage layout (bytes): blocked 8x8-bf16 tiles (128B each).
// A: 16 tiles (4 kt x 4 rt) per half; W: 32 tiles (4 kt x 8 rt) per half.
#define AH_OFF 0
#define AL_OFF 2048
#define WH_OFF 4096
#define WL_OFF 8192
#define STAGE_BYTES 12288
#define SMEM_DYN (2 * STAGE_BYTES + 1024)

// Scratch (no allocations allowed -> __device__ globals)
__device__ int g_flat_idx[NK];
__device__ int g_blockHist[NBLK * NEXP];
__device__ int g_blockBase[NBLK * NEXP];
// Pre-split W, per chunk: 4KB WH tile-layout block + 4KB WL block
__device__ unsigned char g_Wpre[NCHUNK * 8192];

// ---------------------------------------------------------------------------
__device__ __forceinline__ uint32_t smem_u32(const void* p) {
    uint32_t a;
    asm("{ .reg .u64 t; cvta.to.shared.u64 t, %1; cvt.u32.u64 %0, t; }"
        : "=r"(a) : "l"(p));
    return a;
}

#define LDMX4(r0, r1, r2, r3, addr)                                           \
    asm volatile("ldmatrix.sync.aligned.m8n8.x4.shared.b16 {%0,%1,%2,%3}, [%4];" \
        : "=r"(r0), "=r"(r1), "=r"(r2), "=r"(r3) : "r"(addr))

#define MMA_BF16(c, a0, a1, a2, a3, b0, b1)                                   \
    asm volatile(                                                             \
        "mma.sync.aligned.m16n8k16.row.col.f32.bf16.bf16.f32 "                \
        "{%0,%1,%2,%3}, {%4,%5,%6,%7}, {%8,%9}, {%0,%1,%2,%3};"               \
        : "+f"((c)[0]), "+f"((c)[1]), "+f"((c)[2]), "+f"((c)[3])              \
        : "r"(a0), "r"(a1), "r"(a2), "r"(a3), "r"(b0), "r"(b1))

#define CP_ASYNC16(dst, src)                                                  \
    asm volatile("cp.async.cg.shared.global [%0], [%1], 16;"                  \
        :: "r"(dst), "l"(src) : "memory")
#define CP_COMMIT()  asm volatile("cp.async.commit_group;" ::: "memory")
#define CP_WAIT0()   asm volatile("cp.async.wait_group 0;" ::: "memory")

__device__ __forceinline__ uint32_t pack_bf16(__nv_bfloat16 a, __nv_bfloat16 b) {
    __nv_bfloat162 v; v.x = a; v.y = b;
    return *reinterpret_cast<uint32_t*>(&v);
}

__device__ __forceinline__ void split2(float x, float y, uint32_t& hi, uint32_t& lo) {
    __nv_bfloat16 hx = __float2bfloat16(x), hy = __float2bfloat16(y);
    float rx = x - __bfloat162float(hx);
    float ry = y - __bfloat162float(hy);
    hi = pack_bf16(hx, hy);
    lo = pack_bf16(__float2bfloat16(rx), __float2bfloat16(ry));
}

// ---------------------------------------------------------------------------
// Kernel 0: pre-split W into bf16 hi/lo in the swizzled tile layout.
// ---------------------------------------------------------------------------
__global__ __launch_bounds__(512) void wsplit_kernel(const float* __restrict__ W)
{
    const int t   = blockIdx.x;
    const int tid = threadIdx.x;
    const int n   = tid >> 3;
    const int c4  = tid & 7;
    const int kt  = c4 >> 1;
    const int hf  = c4 & 1;

    float4 v = *reinterpret_cast<const float4*>(W + (size_t)n * DIM + t * KC + 4 * c4);
    uint2 h, l;
    split2(v.x, v.y, h.x, l.x);
    split2(v.z, v.w, h.y, l.y);
    uint32_t off = (uint32_t)((kt * 8 + (n >> 3)) * 128 +
                              (((n & 7) ^ (kt << 1)) << 4) + hf * 8);
    *reinterpret_cast<uint2*>(g_Wpre + (size_t)t * 8192 + off) = h;
    *reinterpret_cast<uint2*>(g_Wpre + (size_t)t * 8192 + 4096 + off) = l;
}

// ---------------------------------------------------------------------------
// Kernel 1: BM=32 bf16-split GEMM (512 CTAs) + softmax + top-2 + probs + hist.
// A: LDG+split+STS in-loop; W: cp.async raw copy from g_Wpre, waited AFTER
// the compute phase so the L2 fetch hides under the MMAs.
// ---------------------------------------------------------------------------
__global__ __launch_bounds__(GTHREADS, 4) void gate_gemm_kernel(
    const float* __restrict__ A,   // [NTOK, DIM]
    float* __restrict__ out)
{
    extern __shared__ char dynsm[];
    char* sbase = (char*)(((uintptr_t)dynsm + 1023) & ~(uintptr_t)1023);
    const uint32_t sb = smem_u32(sbase);

    __shared__ int hist[NEXP];

    const int tid  = threadIdx.x;
    const int wid  = tid >> 5;
    const int lane = tid & 31;
    const int g    = lane >> 2;
    const int q    = lane & 3;
    const int lg   = lane >> 3;       // ldmatrix lane group 0..3
    const int lr   = lane & 7;
    const int mG   = wid >> 1;        // rows 16*mG
    const int nG   = wid & 1;         // cols 32*nG
    const int blk  = blockIdx.x;
    const int tok0 = blk * BM;

    if (tid < NEXP) hist[tid] = 0;

    // ---- producer geometry (A only) ----------------------------------------
    const int prow = tid >> 3;        // 0..15
    const int c4   = tid & 7;
    const int kt_p = c4 >> 1;
    const int hf_p = c4 & 1;

    const float4* Ap[2];
    uint32_t stOff[2];
#pragma unroll
    for (int p = 0; p < 2; ++p) {
        int r = prow + 16 * p;        // 0..31
        Ap[p] = reinterpret_cast<const float4*>(A + (size_t)(tok0 + r) * DIM + 4 * c4);
        stOff[p] = (uint32_t)((kt_p * 4 + (r >> 3)) * 128 +
                              (((r & 7) ^ (kt_p << 1)) << 4) + hf_p * 8);
    }

    float4 pa[2];
    auto ldRegsA = [&](int t) {
        const int o = t * 8;          // 32 floats = 8 float4
#pragma unroll
        for (int p = 0; p < 2; ++p) pa[p] = Ap[p][o];
    };
    auto stStageA = [&](int s) {
        char* stg = sbase + s * STAGE_BYTES;
#pragma unroll
        for (int p = 0; p < 2; ++p) {
            uint2 h, l;
            split2(pa[p].x, pa[p].y, h.x, l.x);
            split2(pa[p].z, pa[p].w, h.y, l.y);
            *reinterpret_cast<uint2*>(stg + AH_OFF + stOff[p]) = h;
            *reinterpret_cast<uint2*>(stg + AL_OFF + stOff[p]) = l;
        }
    };
    // W: raw async copy of pre-split chunk (8KB) into stage W region
    auto cpW = [&](int s, int t) {
        uint32_t dst = sb + (uint32_t)(s * STAGE_BYTES + WH_OFF) + (uint32_t)(tid * 64);
        const unsigned char* src = g_Wpre + (size_t)t * 8192 + tid * 64;
#pragma unroll
        for (int gg = 0; gg < 4; ++gg)
            CP_ASYNC16(dst + gg * 16, src + gg * 16);
    };

    float acc[4][4];
#pragma unroll
    for (int nt = 0; nt < 4; ++nt)
#pragma unroll
        for (int c = 0; c < 4; ++c) acc[nt][c] = 0.f;

    const uint32_t aRt = (uint32_t)((2 * mG + (lg & 1)) * 128);
    const uint32_t wRt = (uint32_t)((4 * nG + (lg >> 1)) * 128);

    // ---- prologue ----------------------------------------------------------
    ldRegsA(0);
    stStageA(0);
    cpW(0, 0);
    CP_COMMIT();
    ldRegsA(1);
    CP_WAIT0();
    __syncthreads();

    // ---- mainloop ----------------------------------------------------------
    for (int t = 0; t < NCHUNK; ++t) {
        if (t + 1 < NCHUNK) {
            cpW((t + 1) & 1, t + 1);      // async: W for next chunk
            CP_COMMIT();
            stStageA((t + 1) & 1);        // A convert for next chunk
            if (t + 2 < NCHUNK) ldRegsA(t + 2);
        }

        const uint32_t stg = sb + (uint32_t)((t & 1) * STAGE_BYTES);
#pragma unroll
        for (int ks = 0; ks < 2; ++ks) {
            const int ktA = 2 * ks + (lg >> 1);
            const int ktW = 2 * ks + (lg & 1);
            const uint32_t aAddr = stg + (uint32_t)(ktA * 512) +
                                   (uint32_t)((lr ^ (ktA << 1)) << 4) + aRt;
            const uint32_t wAddr = stg + WH_OFF + (uint32_t)(ktW * 1024) +
                                   (uint32_t)((lr ^ (ktW << 1)) << 4) + wRt;

            uint32_t ah[4], al[4], wh[8], wl[8];
            LDMX4(ah[0], ah[1], ah[2], ah[3], aAddr);
            LDMX4(al[0], al[1], al[2], al[3], aAddr + AL_OFF);
            LDMX4(wh[0], wh[1], wh[2], wh[3], wAddr);
            LDMX4(wh[4], wh[5], wh[6], wh[7], wAddr + 256);
            LDMX4(wl[0], wl[1], wl[2], wl[3], wAddr + 4096);
            LDMX4(wl[4], wl[5], wl[6], wl[7], wAddr + 4096 + 256);

#pragma unroll
            for (int nt = 0; nt < 4; ++nt) {
                const uint32_t bh0 = wh[2 * nt], bh1 = wh[2 * nt + 1];
                const uint32_t bl0 = wl[2 * nt], bl1 = wl[2 * nt + 1];
                MMA_BF16(acc[nt], ah[0], ah[1], ah[2], ah[3], bh0, bh1);
                MMA_BF16(acc[nt], ah[0], ah[1], ah[2], ah[3], bl0, bl1);
                MMA_BF16(acc[nt], al[0], al[1], al[2], al[3], bh0, bh1);
            }
        }

        if (t + 1 < NCHUNK) CP_WAIT0();   // W(t+1) landed (hidden under MMAs)
        __syncthreads();
    }

    // ---- epilogue: logits -> Cs (reuse stage smem) -------------------------
    float* Cs = reinterpret_cast<float*>(sbase);      // [32][66]
#pragma unroll
    for (int nt = 0; nt < 4; ++nt) {
        int row = 16 * mG + g;
        int col = 32 * nG + 8 * nt + 2 * q;
        *reinterpret_cast<float2*>(&Cs[row * 66 + col]) =
            make_float2(acc[nt][0], acc[nt][1]);
        *reinterpret_cast<float2*>(&Cs[(row + 8) * 66 + col]) =
            make_float2(acc[nt][2], acc[nt][3]);
    }
    __syncthreads();

    if (tid < BM) {                     // one thread per token
        const int t = tid;
        float f[64];
        float mx = -1e30f;
#pragma unroll
        for (int e = 0; e < NEXP; e++) { f[e] = Cs[t * 66 + e]; mx = fmaxf(mx, f[e]); }
        float ssum = 0.f;
#pragma unroll
        for (int e = 0; e < NEXP; e++) { f[e] = expf(f[e] - mx); ssum += f[e]; }
        float inv = 1.0f / ssum;
        float v1 = -1.f, v2 = -1.f;
        int i1 = 0, i2 = 0;
#pragma unroll
        for (int e = 0; e < NEXP; e++) {
            float p = f[e] * inv;
            Cs[t * 66 + e] = p;
            if (p > v1)      { v2 = v1; i2 = i1; v1 = p; i1 = e; }
            else if (p > v2) { v2 = p; i2 = e; }
        }
        // combine = softmax over the top-2 prob VALUES (reference quirk)
        float eb = expf(v2 - v1);
        float invd = 1.0f / (1.0f + eb);
        const int token = tok0 + t;
        const int flat = token * 2;
        out[OFF_CW + flat]     = invd;
        out[OFF_CW + flat + 1] = eb * invd;
        g_flat_idx[flat]     = i1;
        g_flat_idx[flat + 1] = i2;
        atomicAdd(&hist[i1], 1);
        atomicAdd(&hist[i2], 1);
    }
    __syncthreads();

    if (tid < NEXP) g_blockHist[blk * NEXP + tid] = hist[tid];

    // coalesced probs writeback (32 tokens x 64 experts)
    float* pout = out + OFF_PROBS + (size_t)tok0 * NEXP;
    for (int idx = tid; idx < BM * NEXP; idx += GTHREADS) {
        int tt = idx >> 6, e = idx & 63;
        pout[idx] = Cs[tt * 66 + e];
    }
}

// ---------------------------------------------------------------------------
// Kernel 2 (1 CTA, 1024 threads): per-expert scan across blocks + offsets
// ---------------------------------------------------------------------------
#define CHUNKB (NBLK / 16)       // 32 blocks per chunk
__global__ __launch_bounds__(1024) void gate_scan_kernel(float* __restrict__ out)
{
    __shared__ int part[16][NEXP];
    __shared__ int totals[NEXP];
    __shared__ int offs[NEXP];
    const int tid = threadIdx.x;
    const int e = tid & 63;
    const int c = tid >> 6;          // chunk 0..15

    int s = 0;
#pragma unroll
    for (int b = c * CHUNKB; b < (c + 1) * CHUNKB; b++) s += g_blockHist[b * NEXP + e];
    part[c][e] = s;
    __syncthreads();

    if (tid < NEXP) {
        int run = 0;
#pragma unroll
        for (int cc = 0; cc < 16; cc++) run += part[cc][e];
        totals[e] = run;
        out[OFF_SPL + e] = (float)run;
    }
    __syncthreads();

    if (tid == 0) {
        int a = 0;
        for (int i = 0; i < NEXP; i++) { offs[i] = a; a += totals[i]; }
    }
    __syncthreads();

    int base = offs[e];
    for (int cc = 0; cc < c; cc++) base += part[cc][e];
#pragma unroll
    for (int b = c * CHUNKB; b < (c + 1) * CHUNKB; b++) {
        g_blockBase[b * NEXP + e] = base;
        base += g_blockHist[b * NEXP + e];
    }
}

// ---------------------------------------------------------------------------
// Kernel 3 (256 x 128): stable intra-block rank + scatter.
// Each scatter block covers 128 flat slots = 2 histogram blocks (BM=32 -> 64
// slots each): loads 2 bases, prefixes within the matching half.
// ---------------------------------------------------------------------------
__global__ __launch_bounds__(128) void gate_scatter_kernel(float* __restrict__ out)
{
    __shared__ int warpHist[4][NEXP];
    __shared__ int base_s[2][NEXP];
    const int tid  = threadIdx.x;
    const int sblk = blockIdx.x;        // 256 scatter blocks x 128 slots
    const int w    = tid >> 5;
    const int lane = tid & 31;
    const int half = tid >> 6;          // which histogram block (0 or 1)

    if (tid < NEXP) base_s[0][tid] = g_blockBase[(sblk * 2) * NEXP + tid];
    else base_s[1][tid - NEXP] = g_blockBase[(sblk * 2 + 1) * NEXP + tid - NEXP];
    for (int i = tid; i < 4 * NEXP; i += 128) (&warpHist[0][0])[i] = 0;
    __syncthreads();

    const int flat = sblk * 128 + tid;  // flat (token, slot) index
    const int e    = g_flat_idx[flat];

    unsigned m     = __match_any_sync(0xffffffffu, e);
    unsigned below = m & ((1u << lane) - 1u);
    int rank = __popc(below);
    if (below == 0) warpHist[w][e] = __popc(m);     // lowest lane of group
    __syncthreads();

    int prev = 0;
    int wlo = half * 2;
#pragma unroll
    for (int ww = 0; ww < 4; ++ww)
        if (ww >= wlo && ww < w) prev += warpHist[ww][e];

    const int pos = base_s[half][e] + prev + rank;
    out[OFF_TOK + pos]  = (float)(flat >> 1);       // token index
    out[OFF_REV + flat] = (float)pos;               // sorted position of flat idx
}

// ---------------------------------------------------------------------------
extern "C" void kernel_launch(void* const* d_in, const int* in_sizes, int n_in,
                              void* d_out, int out_size)
{
    const float* A = (const float*)d_in[0];   // inputs    [16384, 2048] fp32
    const float* W = (const float*)d_in[1];   // wg_weight [64, 2048]    fp32
    float* out = (float*)d_out;

    cudaFuncSetAttribute(gate_gemm_kernel,
                         cudaFuncAttributeMaxDynamicSharedMemorySize, SMEM_DYN);

    wsplit_kernel<<<NCHUNK, 512>>>(W);
    gate_gemm_kernel<<<NBLK, GTHREADS, SMEM_DYN>>>(A, out);
    gate_scan_kernel<<<1, 1024>>>(out);
    gate_scatter_kernel<<<NK / 128, 128>>>(out);
}

// round 12
// speedup vs baseline: 1.2205x; 1.1341x over previous
#include <cuda_runtime.h>
#include <cuda_bf16.h>
#include <math.h>
#include <stdint.h>

// Problem constants
#define NTOK 16384
#define DIM  2048
#define NEXP 64
#define NK   (NTOK * 2)          // 32768 (token, slot) pairs

// GEMM tiling
#define BM 64                    // tokens per CTA
#define KC 32                    // fp32 per K-chunk (2 k16 MMA steps)
#define KSPLIT 2
#define KHALF (DIM / KSPLIT)     // 1024
#define NCHUNK (KHALF / KC)      // 32 chunks per CTA
#define GTHREADS 128
#define NBLK (NTOK / BM)         // 256 M-tiles
#define GRID1 (NBLK * KSPLIT)    // 512 CTAs

// Epilogue/hist geometry
#define EB 128                   // tokens per epilogue block
#define NBLKH (NTOK / EB)        // 128 hist blocks (256 slots each)

// Output layout: concatenation of reference return values (all as fp32)
#define OFF_TOK   0
#define OFF_REV   NK
#define OFF_CW    (2 * NK)
#define OFF_SPL   (3 * NK)
#define OFF_PROBS (3 * NK + NEXP)

// smem stage layout (bytes): blocked 8x8-bf16 tiles (128B each).
#define AH_OFF 0
#define AL_OFF 4096
#define WH_OFF 8192
#define WL_OFF 12288
#define STAGE_BYTES 16384
#define SMEM_DYN (2 * STAGE_BYTES + 1024)

// Scratch (no allocations allowed -> __device__ globals)
__device__ int   g_flat_idx[NK];
__device__ int   g_blockHist[NBLKH * NEXP];
__device__ int   g_blockBase[NBLKH * NEXP];
__device__ float g_partial[KSPLIT][NTOK][NEXP];   // 8 MB split-K partials

// ---------------------------------------------------------------------------
__device__ __forceinline__ uint32_t smem_u32(const void* p) {
    uint32_t a;
    asm("{ .reg .u64 t; cvta.to.shared.u64 t, %1; cvt.u32.u64 %0, t; }"
        : "=r"(a) : "l"(p));
    return a;
}

#define LDMX4(r0, r1, r2, r3, addr)                                           \
    asm volatile("ldmatrix.sync.aligned.m8n8.x4.shared.b16 {%0,%1,%2,%3}, [%4];" \
        : "=r"(r0), "=r"(r1), "=r"(r2), "=r"(r3) : "r"(addr))

#define MMA_BF16(c, a0, a1, a2, a3, b0, b1)                                   \
    asm volatile(                                                             \
        "mma.sync.aligned.m16n8k16.row.col.f32.bf16.bf16.f32 "                \
        "{%0,%1,%2,%3}, {%4,%5,%6,%7}, {%8,%9}, {%0,%1,%2,%3};"               \
        : "+f"((c)[0]), "+f"((c)[1]), "+f"((c)[2]), "+f"((c)[3])              \
        : "r"(a0), "r"(a1), "r"(a2), "r"(a3), "r"(b0), "r"(b1))

__device__ __forceinline__ uint32_t pack_bf16(__nv_bfloat16 a, __nv_bfloat16 b) {
    __nv_bfloat162 v; v.x = a; v.y = b;
    return *reinterpret_cast<uint32_t*>(&v);
}

__device__ __forceinline__ void split2(float x, float y, uint32_t& hi, uint32_t& lo) {
    __nv_bfloat16 hx = __float2bfloat16(x), hy = __float2bfloat16(y);
    float rx = x - __bfloat162float(hx);
    float ry = y - __bfloat162float(hy);
    hi = pack_bf16(hx, hy);
    lo = pack_bf16(__float2bfloat16(rx), __float2bfloat16(ry));
}

// ---------------------------------------------------------------------------
// Kernel 1: split-K bf16-split GEMM -> partial logits.
// blk encodes (m-tile, k-split): mb = blk >> 1, ks = blk & 1.
// Loop body is the validated R6 structure (32 chunks here).
// ---------------------------------------------------------------------------
__global__ __launch_bounds__(GTHREADS, 3) void gate_gemm_kernel(
    const float* __restrict__ A,   // [NTOK, DIM]
    const float* __restrict__ W)   // [NEXP, DIM]
{
    extern __shared__ char dynsm[];
    char* sbase = (char*)(((uintptr_t)dynsm + 1023) & ~(uintptr_t)1023);
    const uint32_t sb = smem_u32(sbase);

    const int tid  = threadIdx.x;
    const int wid  = tid >> 5;
    const int lane = tid & 31;
    const int g    = lane >> 2;
    const int q    = lane & 3;
    const int lg   = lane >> 3;       // ldmatrix lane group 0..3
    const int lr   = lane & 7;
    const int mG   = wid >> 1;        // rows 32*mG
    const int nG   = wid & 1;         // cols 32*nG
    const int mb   = blockIdx.x >> 1;
    const int ksp  = blockIdx.x & 1;
    const int tok0 = mb * BM;
    const int kbase = ksp * KHALF;

    // ---- producer geometry -------------------------------------------------
    const int prow = tid >> 3;        // 0..15
    const int c4   = tid & 7;
    const int kt_p = c4 >> 1;
    const int hf_p = c4 & 1;

    const float4* Ap[4];
    const float4* Wp[4];
    uint32_t stOff[4];
#pragma unroll
    for (int p = 0; p < 4; ++p) {
        int r = prow + 16 * p;
        Ap[p] = reinterpret_cast<const float4*>(A + (size_t)(tok0 + r) * DIM + kbase + 4 * c4);
        Wp[p] = reinterpret_cast<const float4*>(W + (size_t)r * DIM + kbase + 4 * c4);
        stOff[p] = (uint32_t)((kt_p * 8 + (r >> 3)) * 128 +
                              (((r & 7) ^ (kt_p << 1)) << 4) + hf_p * 8);
    }

    float4 pa[4], pw[4];
    auto ldRegs = [&](int t) {
        const int o = t * 8;          // 32 floats = 8 float4
#pragma unroll
        for (int p = 0; p < 4; ++p) { pa[p] = Ap[p][o]; pw[p] = Wp[p][o]; }
    };
    auto stStage = [&](int s) {
        char* stg = sbase + s * STAGE_BYTES;
#pragma unroll
        for (int p = 0; p < 4; ++p) {
            uint2 h, l;
            split2(pa[p].x, pa[p].y, h.x, l.x);
            split2(pa[p].z, pa[p].w, h.y, l.y);
            *reinterpret_cast<uint2*>(stg + AH_OFF + stOff[p]) = h;
            *reinterpret_cast<uint2*>(stg + AL_OFF + stOff[p]) = l;
            split2(pw[p].x, pw[p].y, h.x, l.x);
            split2(pw[p].z, pw[p].w, h.y, l.y);
            *reinterpret_cast<uint2*>(stg + WH_OFF + stOff[p]) = h;
            *reinterpret_cast<uint2*>(stg + WL_OFF + stOff[p]) = l;
        }
    };

    float acc[2][4][4];
#pragma unroll
    for (int mt = 0; mt < 2; ++mt)
#pragma unroll
        for (int nt = 0; nt < 4; ++nt)
#pragma unroll
            for (int c = 0; c < 4; ++c) acc[mt][nt][c] = 0.f;

    const uint32_t aRt = (uint32_t)((4 * mG + (lg & 1)) * 128);
    const uint32_t wRt = (uint32_t)((4 * nG + (lg >> 1)) * 128);

    // prologue
    ldRegs(0);
    stStage(0);
    ldRegs(1);

    for (int t = 0; t < NCHUNK; ++t) {
        __syncthreads();
        if (t + 1 < NCHUNK) {
            stStage((t + 1) & 1);
            if (t + 2 < NCHUNK) ldRegs(t + 2);
        }
        const uint32_t stg = sb + (uint32_t)((t & 1) * STAGE_BYTES);

#pragma unroll
        for (int ks = 0; ks < 2; ++ks) {
            const int ktA = 2 * ks + (lg >> 1);
            const int ktW = 2 * ks + (lg & 1);
            const uint32_t aAddr = stg + (uint32_t)(ktA * 1024) +
                                   (uint32_t)((lr ^ (ktA << 1)) << 4) + aRt;
            const uint32_t wAddr = stg + WH_OFF + (uint32_t)(ktW * 1024) +
                                   (uint32_t)((lr ^ (ktW << 1)) << 4) + wRt;

            uint32_t ah[8], al[8], wh[8], wl[8];
            LDMX4(ah[0], ah[1], ah[2], ah[3], aAddr);
            LDMX4(ah[4], ah[5], ah[6], ah[7], aAddr + 256);
            LDMX4(al[0], al[1], al[2], al[3], aAddr + AL_OFF);
            LDMX4(al[4], al[5], al[6], al[7], aAddr + AL_OFF + 256);
            LDMX4(wh[0], wh[1], wh[2], wh[3], wAddr);
            LDMX4(wh[4], wh[5], wh[6], wh[7], wAddr + 256);
            LDMX4(wl[0], wl[1], wl[2], wl[3], wAddr + 4096);
            LDMX4(wl[4], wl[5], wl[6], wl[7], wAddr + 4096 + 256);

#pragma unroll
            for (int nt = 0; nt < 4; ++nt) {
                const uint32_t bh0 = wh[2 * nt], bh1 = wh[2 * nt + 1];
                const uint32_t bl0 = wl[2 * nt], bl1 = wl[2 * nt + 1];
#pragma unroll
                for (int mt = 0; mt < 2; ++mt) {
                    uint32_t* aH = &ah[4 * mt];
                    uint32_t* aL = &al[4 * mt];
                    MMA_BF16(acc[mt][nt], aH[0], aH[1], aH[2], aH[3], bh0, bh1);
                    MMA_BF16(acc[mt][nt], aH[0], aH[1], aH[2], aH[3], bl0, bl1);
                    MMA_BF16(acc[mt][nt], aL[0], aL[1], aL[2], aL[3], bh0, bh1);
                }
            }
        }
    }

    // ---- stage partial logits in smem (stride 68 for 16B-aligned rows) -----
    __syncthreads();
    float* Cs = reinterpret_cast<float*>(sbase);      // [64][68]
#pragma unroll
    for (int mt = 0; mt < 2; ++mt)
#pragma unroll
        for (int nt = 0; nt < 4; ++nt) {
            int row = 32 * mG + 16 * mt + g;
            int col = 32 * nG + 8 * nt + 2 * q;
            *reinterpret_cast<float2*>(&Cs[row * 68 + col]) =
                make_float2(acc[mt][nt][0], acc[mt][nt][1]);
            *reinterpret_cast<float2*>(&Cs[(row + 8) * 68 + col]) =
                make_float2(acc[mt][nt][2], acc[mt][nt][3]);
        }
    __syncthreads();

    // coalesced partial writeback: 64 tokens x 64 experts, float4
    float4* pout = reinterpret_cast<float4*>(&g_partial[ksp][tok0][0]);
#pragma unroll
    for (int i = 0; i < 8; ++i) {
        int idx4 = tid + i * GTHREADS;        // 0..1023
        int row = idx4 >> 4, c16 = idx4 & 15;
        pout[idx4] = *reinterpret_cast<const float4*>(&Cs[row * 68 + 4 * c16]);
    }
}

// ---------------------------------------------------------------------------
// Kernel 1b (epilogue): sum partials, softmax, top-2, combine, probs, hist.
// grid NBLKH x 128 threads (one thread per token).
// ---------------------------------------------------------------------------
__global__ __launch_bounds__(EB) void gate_epilogue_kernel(float* __restrict__ out)
{
    __shared__ int hist[NEXP];
    const int tid   = threadIdx.x;
    const int eb    = blockIdx.x;
    const int token = eb * EB + tid;

    if (tid < NEXP) hist[tid] = 0;
    __syncthreads();

    float f[64];
    {
        const float4* p0 = reinterpret_cast<const float4*>(&g_partial[0][token][0]);
        const float4* p1 = reinterpret_cast<const float4*>(&g_partial[1][token][0]);
#pragma unroll
        for (int i = 0; i < 16; ++i) {
            float4 a = p0[i], b = p1[i];
            f[4 * i]     = a.x + b.x;
            f[4 * i + 1] = a.y + b.y;
            f[4 * i + 2] = a.z + b.z;
            f[4 * i + 3] = a.w + b.w;
        }
    }

    float mx = -1e30f;
#pragma unroll
    for (int e = 0; e < NEXP; e++) mx = fmaxf(mx, f[e]);
    float ssum = 0.f;
#pragma unroll
    for (int e = 0; e < NEXP; e++) { f[e] = expf(f[e] - mx); ssum += f[e]; }
    float inv = 1.0f / ssum;
    float v1 = -1.f, v2 = -1.f;
    int i1 = 0, i2 = 0;
#pragma unroll
    for (int e = 0; e < NEXP; e++) {
        float p = f[e] * inv;
        f[e] = p;
        if (p > v1)      { v2 = v1; i2 = i1; v1 = p; i1 = e; }
        else if (p > v2) { v2 = p; i2 = e; }
    }
    // combine = softmax over the top-2 prob VALUES (reference quirk)
    float eb2 = expf(v2 - v1);
    float invd = 1.0f / (1.0f + eb2);
    const int flat = token * 2;
    out[OFF_CW + flat]     = invd;
    out[OFF_CW + flat + 1] = eb2 * invd;
    g_flat_idx[flat]     = i1;
    g_flat_idx[flat + 1] = i2;
    atomicAdd(&hist[i1], 1);
    atomicAdd(&hist[i2], 1);

    // probs: contiguous 256B per thread
    float4* pp = reinterpret_cast<float4*>(out + OFF_PROBS + (size_t)token * NEXP);
#pragma unroll
    for (int k = 0; k < 16; k++)
        pp[k] = make_float4(f[4 * k], f[4 * k + 1], f[4 * k + 2], f[4 * k + 3]);

    __syncthreads();
    if (tid < NEXP) g_blockHist[eb * NEXP + tid] = hist[tid];
}

// ---------------------------------------------------------------------------
// Kernel 2 (1 CTA, 1024 threads): per-expert scan across hist blocks.
// ---------------------------------------------------------------------------
#define CHUNKB (NBLKH / 16)      // 8 blocks per chunk
__global__ __launch_bounds__(1024) void gate_scan_kernel(float* __restrict__ out)
{
    __shared__ int part[16][NEXP];
    __shared__ int totals[NEXP];
    __shared__ int offs[NEXP];
    const int tid = threadIdx.x;
    const int e = tid & 63;
    const int c = tid >> 6;          // chunk 0..15

    int s = 0;
#pragma unroll
    for (int b = c * CHUNKB; b < (c + 1) * CHUNKB; b++) s += g_blockHist[b * NEXP + e];
    part[c][e] = s;
    __syncthreads();

    if (tid < NEXP) {
        int run = 0;
#pragma unroll
        for (int cc = 0; cc < 16; cc++) run += part[cc][e];
        totals[e] = run;
        out[OFF_SPL + e] = (float)run;
    }
    __syncthreads();

    if (tid == 0) {
        int a = 0;
        for (int i = 0; i < NEXP; i++) { offs[i] = a; a += totals[i]; }
    }
    __syncthreads();

    int base = offs[e];
    for (int cc = 0; cc < c; cc++) base += part[cc][e];
#pragma unroll
    for (int b = c * CHUNKB; b < (c + 1) * CHUNKB; b++) {
        g_blockBase[b * NEXP + e] = base;
        base += g_blockHist[b * NEXP + e];
    }
}

// ---------------------------------------------------------------------------
// Kernel 3 (NBLKH x 256): stable intra-block rank + scatter.
// Block covers 256 flat slots = one hist block (EB=128 tokens).
// ---------------------------------------------------------------------------
__global__ __launch_bounds__(256) void gate_scatter_kernel(float* __restrict__ out)
{
    __shared__ int warpHist[8][NEXP];
    __shared__ int base_s[NEXP];
    const int tid  = threadIdx.x;
    const int blk  = blockIdx.x;
    const int w    = tid >> 5;
    const int lane = tid & 31;

    if (tid < NEXP) base_s[tid] = g_blockBase[blk * NEXP + tid];
    for (int i = tid; i < 8 * NEXP; i += 256) (&warpHist[0][0])[i] = 0;
    __syncthreads();

    const int flat = blk * 256 + tid;
    const int e    = g_flat_idx[flat];

    unsigned m     = __match_any_sync(0xffffffffu, e);
    unsigned below = m & ((1u << lane) - 1u);
    int rank = __popc(below);
    if (below == 0) warpHist[w][e] = __popc(m);     // lowest lane of group
    __syncthreads();

    int prev = 0;
#pragma unroll
    for (int ww = 0; ww < 7; ++ww)
        if (ww < w) prev += warpHist[ww][e];

    const int pos = base_s[e] + prev + rank;
    out[OFF_TOK + pos]  = (float)(flat >> 1);       // token index
    out[OFF_REV + flat] = (float)pos;               // sorted position of flat idx
}

// ---------------------------------------------------------------------------
extern "C" void kernel_launch(void* const* d_in, const int* in_sizes, int n_in,
                              void* d_out, int out_size)
{
    const float* A = (const float*)d_in[0];   // inputs    [16384, 2048] fp32
    const float* W = (const float*)d_in[1];   // wg_weight [64, 2048]    fp32
    float* out = (float*)d_out;

    cudaFuncSetAttribute(gate_gemm_kernel,
                         cudaFuncAttributeMaxDynamicSharedMemorySize, SMEM_DYN);

    gate_gemm_kernel<<<GRID1, GTHREADS, SMEM_DYN>>>(A, W);
    gate_epilogue_kernel<<<NBLKH, EB>>>(out);
    gate_scan_kernel<<<1, 1024>>>(out);
    gate_scatter_kernel<<<NBLKH, 256>>>(out);
}

// round 13
// speedup vs baseline: 1.3296x; 1.0894x over previous
#include <cuda_runtime.h>
#include <cuda_bf16.h>
#include <math.h>
#include <stdint.h>

// Problem constants
#define NTOK 16384
#define DIM  2048
#define NEXP 64
#define NK   (NTOK * 2)          // 32768 (token, slot) pairs

// GEMM tiling
#define BM 64                    // tokens per CTA
#define KC 32                    // fp32 per K-chunk (2 k16 MMA steps)
#define NCHUNK (DIM / KC)        // 64
#define GTHREADS 256             // 8 warps: warp tile M16 x N32
#define NBLK (NTOK / BM)         // 256 CTAs

// Output layout: concatenation of reference return values (all as fp32)
#define OFF_TOK   0
#define OFF_REV   NK
#define OFF_CW    (2 * NK)
#define OFF_SPL   (3 * NK)
#define OFF_PROBS (3 * NK + NEXP)

// smem stage layout (bytes): blocked 8x8-bf16 tiles (128B each).
#define AH_OFF 0
#define AL_OFF 4096
#define WH_OFF 8192
#define WL_OFF 12288
#define STAGE_BYTES 16384
#define SMEM_DYN (2 * STAGE_BYTES + 1024)

// Scratch (no allocations allowed -> __device__ globals)
__device__ int g_flat_idx[NK];
__device__ int g_blockHist[NBLK * NEXP];
__device__ int g_blockBase[NBLK * NEXP];

// ---------------------------------------------------------------------------
__device__ __forceinline__ uint32_t smem_u32(const void* p) {
    uint32_t a;
    asm("{ .reg .u64 t; cvta.to.shared.u64 t, %1; cvt.u32.u64 %0, t; }"
        : "=r"(a) : "l"(p));
    return a;
}

#define LDMX4(r0, r1, r2, r3, addr)                                           \
    asm volatile("ldmatrix.sync.aligned.m8n8.x4.shared.b16 {%0,%1,%2,%3}, [%4];" \
        : "=r"(r0), "=r"(r1), "=r"(r2), "=r"(r3) : "r"(addr))

#define MMA_BF16(c, a0, a1, a2, a3, b0, b1)                                   \
    asm volatile(                                                             \
        "mma.sync.aligned.m16n8k16.row.col.f32.bf16.bf16.f32 "                \
        "{%0,%1,%2,%3}, {%4,%5,%6,%7}, {%8,%9}, {%0,%1,%2,%3};"               \
        : "+f"((c)[0]), "+f"((c)[1]), "+f"((c)[2]), "+f"((c)[3])              \
        : "r"(a0), "r"(a1), "r"(a2), "r"(a3), "r"(b0), "r"(b1))

__device__ __forceinline__ uint32_t pack_bf16(__nv_bfloat16 a, __nv_bfloat16 b) {
    __nv_bfloat162 v; v.x = a; v.y = b;
    return *reinterpret_cast<uint32_t*>(&v);
}

__device__ __forceinline__ void split2(float x, float y, uint32_t& hi, uint32_t& lo) {
    __nv_bfloat16 hx = __float2bfloat16(x), hy = __float2bfloat16(y);
    float rx = x - __bfloat162float(hx);
    float ry = y - __bfloat162float(hy);
    hi = pack_bf16(hx, hy);
    lo = pack_bf16(__float2bfloat16(rx), __float2bfloat16(ry));
}

// ---------------------------------------------------------------------------
// Kernel 1: bf16-split mma.sync GEMM + softmax + top-2 + combine + probs +
// hist.  8 warps: warp = (mG = wid>>1, rows 16*mG) x (nG = wid&1, cols 32*nG).
// Same CTA tile / smem layout / MMA count as the 128-thread champion; work is
// spread over 2x warps for latency hiding at occupancy 2 (16 warps/SM).
// ---------------------------------------------------------------------------
__global__ __launch_bounds__(GTHREADS, 2) void gate_gemm_kernel(
    const float* __restrict__ A,   // [NTOK, DIM]
    const float* __restrict__ W,   // [NEXP, DIM]
    float* __restrict__ out)
{
    extern __shared__ char dynsm[];
    char* sbase = (char*)(((uintptr_t)dynsm + 1023) & ~(uintptr_t)1023);
    const uint32_t sb = smem_u32(sbase);

    __shared__ int hist[NEXP];

    const int tid  = threadIdx.x;
    const int wid  = tid >> 5;
    const int lane = tid & 31;
    const int g    = lane >> 2;
    const int q    = lane & 3;
    const int lg   = lane >> 3;       // ldmatrix lane group 0..3
    const int lr   = lane & 7;
    const int mG   = wid >> 1;        // rows 16*mG  (0..3)
    const int nG   = wid & 1;         // cols 32*nG
    const int blk  = blockIdx.x;
    const int tok0 = blk * BM;

    if (tid < NEXP) hist[tid] = 0;

    // ---- producer geometry: 256 threads, 2 rows each for A and W -----------
    const int prow = tid >> 3;        // 0..31
    const int c4   = tid & 7;
    const int kt_p = c4 >> 1;
    const int hf_p = c4 & 1;

    const float4* Ap[2];
    const float4* Wp[2];
    uint32_t stOff[2];
#pragma unroll
    for (int p = 0; p < 2; ++p) {
        int r = prow + 32 * p;        // 0..63
        Ap[p] = reinterpret_cast<const float4*>(A + (size_t)(tok0 + r) * DIM + 4 * c4);
        Wp[p] = reinterpret_cast<const float4*>(W + (size_t)r * DIM + 4 * c4);
        stOff[p] = (uint32_t)((kt_p * 8 + (r >> 3)) * 128 +
                              (((r & 7) ^ (kt_p << 1)) << 4) + hf_p * 8);
    }

    float4 pa[2], pw[2];
    auto ldRegs = [&](int t) {
        const int o = t * 8;          // 32 floats = 8 float4
#pragma unroll
        for (int p = 0; p < 2; ++p) { pa[p] = Ap[p][o]; pw[p] = Wp[p][o]; }
    };
    auto stStage = [&](int s) {
        char* stg = sbase + s * STAGE_BYTES;
#pragma unroll
        for (int p = 0; p < 2; ++p) {
            uint2 h, l;
            split2(pa[p].x, pa[p].y, h.x, l.x);
            split2(pa[p].z, pa[p].w, h.y, l.y);
            *reinterpret_cast<uint2*>(stg + AH_OFF + stOff[p]) = h;
            *reinterpret_cast<uint2*>(stg + AL_OFF + stOff[p]) = l;
            split2(pw[p].x, pw[p].y, h.x, l.x);
            split2(pw[p].z, pw[p].w, h.y, l.y);
            *reinterpret_cast<uint2*>(stg + WH_OFF + stOff[p]) = h;
            *reinterpret_cast<uint2*>(stg + WL_OFF + stOff[p]) = l;
        }
    };

    float acc[4][4];
#pragma unroll
    for (int nt = 0; nt < 4; ++nt)
#pragma unroll
        for (int c = 0; c < 4; ++c) acc[nt][c] = 0.f;

    // consumer lane-constant pieces
    const uint32_t aRt = (uint32_t)((2 * mG + (lg & 1)) * 128);
    const uint32_t wRt = (uint32_t)((4 * nG + (lg >> 1)) * 128);

    // prologue
    ldRegs(0);
    stStage(0);
    ldRegs(1);

    for (int t = 0; t < NCHUNK; ++t) {
        __syncthreads();
        if (t + 1 < NCHUNK) {
            stStage((t + 1) & 1);
            if (t + 2 < NCHUNK) ldRegs(t + 2);
        }
        const uint32_t stg = sb + (uint32_t)((t & 1) * STAGE_BYTES);

#pragma unroll
        for (int ks = 0; ks < 2; ++ks) {
            const int ktA = 2 * ks + (lg >> 1);
            const int ktW = 2 * ks + (lg & 1);
            const uint32_t aAddr = stg + (uint32_t)(ktA * 1024) +
                                   (uint32_t)((lr ^ (ktA << 1)) << 4) + aRt;
            const uint32_t wAddr = stg + WH_OFF + (uint32_t)(ktW * 1024) +
                                   (uint32_t)((lr ^ (ktW << 1)) << 4) + wRt;

            uint32_t ah[4], al[4], wh[8], wl[8];
            LDMX4(ah[0], ah[1], ah[2], ah[3], aAddr);
            LDMX4(al[0], al[1], al[2], al[3], aAddr + AL_OFF);
            LDMX4(wh[0], wh[1], wh[2], wh[3], wAddr);
            LDMX4(wh[4], wh[5], wh[6], wh[7], wAddr + 256);
            LDMX4(wl[0], wl[1], wl[2], wl[3], wAddr + 4096);
            LDMX4(wl[4], wl[5], wl[6], wl[7], wAddr + 4096 + 256);

#pragma unroll
            for (int nt = 0; nt < 4; ++nt) {
                const uint32_t bh0 = wh[2 * nt], bh1 = wh[2 * nt + 1];
                const uint32_t bl0 = wl[2 * nt], bl1 = wl[2 * nt + 1];
                MMA_BF16(acc[nt], ah[0], ah[1], ah[2], ah[3], bh0, bh1);
                MMA_BF16(acc[nt], ah[0], ah[1], ah[2], ah[3], bl0, bl1);
                MMA_BF16(acc[nt], al[0], al[1], al[2], al[3], bh0, bh1);
            }
        }
    }

    // ---- epilogue: logits -> Cs (reuse stage smem) -------------------------
    __syncthreads();
    float* Cs = reinterpret_cast<float*>(sbase);      // [64][66]
#pragma unroll
    for (int nt = 0; nt < 4; ++nt) {
        int row = 16 * mG + g;
        int col = 32 * nG + 8 * nt + 2 * q;
        *reinterpret_cast<float2*>(&Cs[row * 66 + col]) =
            make_float2(acc[nt][0], acc[nt][1]);
        *reinterpret_cast<float2*>(&Cs[(row + 8) * 66 + col]) =
            make_float2(acc[nt][2], acc[nt][3]);
    }
    __syncthreads();

    if (tid < BM) {                     // one thread per token
        const int t = tid;
        float f[64];
        float mx = -1e30f;
#pragma unroll
        for (int e = 0; e < NEXP; e++) { f[e] = Cs[t * 66 + e]; mx = fmaxf(mx, f[e]); }
        float ssum = 0.f;
#pragma unroll
        for (int e = 0; e < NEXP; e++) { f[e] = expf(f[e] - mx); ssum += f[e]; }
        float inv = 1.0f / ssum;
        float v1 = -1.f, v2 = -1.f;
        int i1 = 0, i2 = 0;
#pragma unroll
        for (int e = 0; e < NEXP; e++) {
            float p = f[e] * inv;
            Cs[t * 66 + e] = p;         // probs back to smem for coalesced copy
            if (p > v1)      { v2 = v1; i2 = i1; v1 = p; i1 = e; }
            else if (p > v2) { v2 = p; i2 = e; }
        }
        // combine = softmax over the top-2 prob VALUES (reference quirk)
        float eb = expf(v2 - v1);
        float invd = 1.0f / (1.0f + eb);
        const int token = tok0 + t;
        const int flat = token * 2;
        out[OFF_CW + flat]     = invd;
        out[OFF_CW + flat + 1] = eb * invd;
        g_flat_idx[flat]     = i1;
        g_flat_idx[flat + 1] = i2;
        atomicAdd(&hist[i1], 1);
        atomicAdd(&hist[i2], 1);
    }
    __syncthreads();

    if (tid < NEXP) g_blockHist[blk * NEXP + tid] = hist[tid];

    // coalesced probs writeback
    float* pout = out + OFF_PROBS + (size_t)tok0 * NEXP;
    for (int idx = tid; idx < BM * NEXP; idx += GTHREADS) {
        int tt = idx >> 6, e = idx & 63;
        pout[idx] = Cs[tt * 66 + e];
    }
}

// ---------------------------------------------------------------------------
// Kernel 2 (1 CTA, 1024 threads): per-expert scan across blocks + offsets
// ---------------------------------------------------------------------------
#define CHUNKB (NBLK / 16)       // 16 blocks per chunk
__global__ __launch_bounds__(1024) void gate_scan_kernel(float* __restrict__ out)
{
    __shared__ int part[16][NEXP];
    __shared__ int totals[NEXP];
    __shared__ int offs[NEXP];
    const int tid = threadIdx.x;
    const int e = tid & 63;
    const int c = tid >> 6;          // chunk 0..15

    int s = 0;
#pragma unroll
    for (int b = c * CHUNKB; b < (c + 1) * CHUNKB; b++) s += g_blockHist[b * NEXP + e];
    part[c][e] = s;
    __syncthreads();

    if (tid < NEXP) {
        int run = 0;
#pragma unroll
        for (int cc = 0; cc < 16; cc++) run += part[cc][e];
        totals[e] = run;
        out[OFF_SPL + e] = (float)run;
    }
    __syncthreads();

    if (tid == 0) {
        int a = 0;
        for (int i = 0; i < NEXP; i++) { offs[i] = a; a += totals[i]; }
    }
    __syncthreads();

    int base = offs[e];
    for (int cc = 0; cc < c; cc++) base += part[cc][e];
#pragma unroll
    for (int b = c * CHUNKB; b < (c + 1) * CHUNKB; b++) {
        g_blockBase[b * NEXP + e] = base;
        base += g_blockHist[b * NEXP + e];
    }
}

// ---------------------------------------------------------------------------
// Kernel 3 (NBLK x 128): stable intra-block rank + scatter.
// Block covers 128 flat slots = one hist block (BM=64 tokens x 2 slots).
// ---------------------------------------------------------------------------
__global__ __launch_bounds__(128) void gate_scatter_kernel(float* __restrict__ out)
{
    __shared__ int warpHist[4][NEXP];
    __shared__ int base_s[NEXP];
    const int tid  = threadIdx.x;
    const int blk  = blockIdx.x;
    const int w    = tid >> 5;
    const int lane = tid & 31;

    if (tid < NEXP) base_s[tid] = g_blockBase[blk * NEXP + tid];
    for (int i = tid; i < 4 * NEXP; i += 128) (&warpHist[0][0])[i] = 0;
    __syncthreads();

    const int flat = blk * 128 + tid;
    const int e    = g_flat_idx[flat];

    unsigned m     = __match_any_sync(0xffffffffu, e);
    unsigned below = m & ((1u << lane) - 1u);
    int rank = __popc(below);
    if (below == 0) warpHist[w][e] = __popc(m);     // lowest lane of group
    __syncthreads();

    int prev = 0;
#pragma unroll
    for (int ww = 0; ww < 3; ++ww)
        if (ww < w) prev += warpHist[ww][e];

    const int pos = base_s[e] + prev + rank;
    out[OFF_TOK + pos]  = (float)(flat >> 1);       // token index
    out[OFF_REV + flat] = (float)pos;               // sorted position of flat idx
}

// ---------------------------------------------------------------------------
extern "C" void kernel_launch(void* const* d_in, const int* in_sizes, int n_in,
                              void* d_out, int out_size)
{
    const float* A = (const float*)d_in[0];   // inputs    [16384, 2048] fp32
    const float* W = (const float*)d_in[1];   // wg_weight [64, 2048]    fp32
    float* out = (float*)d_out;

    cudaFuncSetAttribute(gate_gemm_kernel,
                         cudaFuncAttributeMaxDynamicSharedMemorySize, SMEM_DYN);

    gate_gemm_kernel<<<NBLK, GTHREADS, SMEM_DYN>>>(A, W, out);
    gate_scan_kernel<<<1, 1024>>>(out);
    gate_scatter_kernel<<<NK / 128, 128>>>(out);
}